// round 11
// baseline (speedup 1.0000x reference)
#include <cuda_runtime.h>

#define BB 1024
#define DD 256
#define HH 32
#define ROWS_PER_BLK 4

// Column tables: exp(+W)/exp(-W) interleaved by j-pair, [16][DD] float2 — coalesced
// across k in the per-dim passes.  Row tables: [DD][HH] — coalesced across j for the
// rank-1 kstar-row gather.
__device__ float  g_ewp[HH * DD];
__device__ float  g_ewm[HH * DD];
__device__ float  g_ewpR[DD * HH];
__device__ float  g_ewmR[DD * HH];
__device__ float2 g_eb[DD];          // (exp(+b/2), exp(-b/2))
__device__ float  g_E[BB * HH];      // E_j(row) = exp((x@W)_j + c_j)

// Prep: blocks 0..7 build tables; blocks 8..8+BB/8-1 compute E, 8 rows per block.
__global__ __launch_bounds__(256) void prep_kernel(
    const float* __restrict__ x,
    const float* __restrict__ W,
    const float* __restrict__ b,
    const float* __restrict__ c)
{
    const int bid = blockIdx.x;
    const int tid = threadIdx.x;
    if (bid < 8) {
        for (int t = bid * 256 + tid; t < DD * HH; t += 8 * 256) {
            int d = t >> 5;
            int j = t & 31;
            float w  = W[t];
            float ep = expf(w);
            float em = expf(-w);
            int idx = (j >> 1) * (DD * 2) + d * 2 + (j & 1);
            g_ewp[idx] = ep;
            g_ewm[idx] = em;
            g_ewpR[t] = ep;          // t = d*HH + j: row-major copy
            g_ewmR[t] = em;
        }
        int t = bid * 256 + tid;
        if (t < DD) {
            float bv = b[t];
            g_eb[t] = make_float2(expf(0.5f * bv), expf(-0.5f * bv));
        }
        cudaTriggerProgrammaticLaunchCompletion();
        return;
    }

    // ---- E for 8 rows: warp w covers d in [32w,32w+32), lane = j.
    //      Each W value is loaded once and reused across 8 rows (8 masks). ----
    __shared__ float ap[8][8][32];           // [warp][row][j]
    const int row0 = (bid - 8) * 8;
    const int w    = tid >> 5;
    const int lane = tid & 31;

    unsigned m[8];
    #pragma unroll
    for (int r = 0; r < 8; ++r)
        m[r] = __ballot_sync(0xffffffffu, x[(row0 + r) * DD + w * 32 + lane] != 0.0f);

    const float* Wb = W + (w * 32) * HH + lane;
    float acc[8] = {0.f, 0.f, 0.f, 0.f, 0.f, 0.f, 0.f, 0.f};
    #pragma unroll
    for (int i = 0; i < 32; ++i) {
        float wv = Wb[i * HH];
        #pragma unroll
        for (int r = 0; r < 8; ++r)
            if (m[r] & (1u << i)) acc[r] += wv;
    }
    #pragma unroll
    for (int r = 0; r < 8; ++r) ap[w][r][lane] = acc[r];
    __syncthreads();

    // warp w finishes row (row0 + w)
    float a = c[lane];
    #pragma unroll
    for (int ww = 0; ww < 8; ++ww) a += ap[ww][w][lane];
    g_E[(row0 + w) * HH + lane] = expf(a);
    cudaTriggerProgrammaticLaunchCompletion();
}

__device__ __forceinline__ unsigned fmono(float f) {
    unsigned u = __float_as_uint(f);
    return (u & 0x80000000u) ? ~u : (u | 0x80000000u);
}

__global__ __launch_bounds__(128, 8) void gwg_kernel(
    const float* __restrict__ x,
    const float* __restrict__ gum,
    const float* __restrict__ acc,
    float* __restrict__ out)
{
    __shared__ float xs[DD];
    __shared__ __align__(16) float sEf[4][HH];   // per-warp copy of E_j
    __shared__ __align__(16) float sE2[4][HH];   // per-warp copy of E'_j
    __shared__ float sredf[4];
    __shared__ uint2 sredk[4];                   // (fmono(key), idx) per warp

    const int tid  = threadIdx.x;
    const int w    = tid >> 5;
    const int lane = tid & 31;
    const int k0   = tid;          // dims tid and tid+128
    const int k1   = tid + 128;

    // wait for prep's global writes (tables, g_eb, g_E) to be visible
    cudaGridDependencySynchronize();

    const float2 eb0 = g_eb[k0];   // row-invariant
    const float2 eb1 = g_eb[k1];

    for (int r = 0; r < ROWS_PER_BLK; ++r) {
        const int row = blockIdx.x * ROWS_PER_BLK + r;

        float xk0 = x[row * DD + k0];
        float xk1 = x[row * DD + k1];
        float u0  = gum[row * DD + k0];
        float u1  = gum[row * DD + k1];
        float au  = acc[row];
        float E   = g_E[row * HH + lane];

        float z0 = -logf(u0 + 1e-9f) + 1e-9f;
        float z1 = -logf(u1 + 1e-9f) + 1e-9f;

        __syncthreads();                        // WAR: xs/sredf of previous row
        xs[k0] = xk0;
        xs[k1] = xk1;
        sEf[w][lane] = E;
        __syncwarp();

        // ---- forward: p~_k = prod_j (1 + E_j e^{delta_k w_kj}) ----
        const float2* t0 = (const float2*)((xk0 == 0.0f) ? g_ewp : g_ewm);
        const float2* t1 = (const float2*)((xk1 == 0.0f) ? g_ewp : g_ewm);
        const float ebf0 = (xk0 == 0.0f) ? eb0.x : eb0.y;
        const float ebf1 = (xk1 == 0.0f) ? eb1.x : eb1.y;
        const float4* sE4f = (const float4*)sEf[w];

        float p0 = 1.f, p1 = 1.f, p2 = 1.f, p3 = 1.f;
        float r0 = 1.f, r1 = 1.f, r2 = 1.f, r3 = 1.f;
        #pragma unroll
        for (int jp = 0; jp < 16; jp += 2) {
            float4 Ev = sE4f[jp >> 1];
            float2 aA = __ldg(&t0[jp * DD + k0]);
            float2 aB = __ldg(&t0[(jp + 1) * DD + k0]);
            float2 bA = __ldg(&t1[jp * DD + k1]);
            float2 bB = __ldg(&t1[(jp + 1) * DD + k1]);
            p0 *= fmaf(Ev.x, aA.x, 1.f);
            p1 *= fmaf(Ev.y, aA.y, 1.f);
            p2 *= fmaf(Ev.z, aB.x, 1.f);
            p3 *= fmaf(Ev.w, aB.y, 1.f);
            r0 *= fmaf(Ev.x, bA.x, 1.f);
            r1 *= fmaf(Ev.y, bA.y, 1.f);
            r2 *= fmaf(Ev.z, bB.x, 1.f);
            r3 *= fmaf(Ev.w, bB.y, 1.f);
        }
        float ek0 = ebf0 * sqrtf((p0 * p1) * (p2 * p3));
        float ek1 = ebf1 * sqrtf((r0 * r1) * (r2 * r3));

        // gumbel-max in exp domain: argmax(l+g) == argmax(ek / z); keys > 0
        float key0 = ek0 / z0;
        float key1 = ek1 / z1;

        float key; int ki;
        if (key0 >= key1) { key = key0; ki = k0; } else { key = key1; ki = k1; }

        // warp sum (5 shfl) + warp argmax (redux + ballot + 1 shfl)
        float s = ek0 + ek1;
        #pragma unroll
        for (int off = 16; off; off >>= 1) s += __shfl_xor_sync(0xffffffffu, s, off);
        unsigned km   = fmono(key);
        unsigned wmax = __reduce_max_sync(0xffffffffu, km);
        unsigned ball = __ballot_sync(0xffffffffu, km == wmax);
        int      wki  = __shfl_sync(0xffffffffu, ki, __ffs(ball) - 1);
        if (lane == 0) { sredf[w] = s; sredk[w] = make_uint2(wmax, (unsigned)wki); }
        __syncthreads();                        // B2 (genuine combine)

        // ---- every thread combines 4 warp partials via broadcast LDS ----
        float Sf;
        int   kstar;
        {
            Sf = (sredf[0] + sredf[1]) + (sredf[2] + sredf[3]);
            uint2 c0 = sredk[0], c1 = sredk[1], c2 = sredk[2], c3 = sredk[3];
            uint2 mA = (c1.x > c0.x || (c1.x == c0.x && c1.y < c0.y)) ? c1 : c0;
            uint2 mB = (c3.x > c2.x || (c3.x == c2.x && c3.y < c2.y)) ? c3 : c2;
            uint2 mm = (mB.x > mA.x || (mB.x == mA.x && mB.y < mA.y)) ? mB : mA;
            kstar = (int)mm.y;
        }

        // ---- rank-1 update, per-warp redundant: coalesced row read ----
        float Rt;
        {
            float xks = xs[kstar];              // visible: written pre-B2
            const float* rowt = (xks == 0.0f) ? g_ewpR : g_ewmR;
            float mj  = __ldg(&rowt[kstar * HH + lane]);
            float E2  = E * mj;
            sE2[w][lane] = E2;
            float rr = (1.f + E2) / (1.f + E);
            #pragma unroll
            for (int off = 16; off; off >>= 1) rr *= __shfl_xor_sync(0xffffffffu, rr, off);
            Rt = rr;
            __syncwarp();
        }

        // ---- reverse pass at x_delta: tables flip only for the kstar dim ----
        const float2* t0r = (k0 == kstar) ? ((xk0 == 0.0f) ? (const float2*)g_ewm : (const float2*)g_ewp) : t0;
        const float2* t1r = (k1 == kstar) ? ((xk1 == 0.0f) ? (const float2*)g_ewm : (const float2*)g_ewp) : t1;
        const float ebr0 = (k0 == kstar) ? ((xk0 == 0.0f) ? eb0.y : eb0.x) : ebf0;
        const float ebr1 = (k1 == kstar) ? ((xk1 == 0.0f) ? eb1.y : eb1.x) : ebf1;
        const float4* sE42 = (const float4*)sE2[w];

        float q0 = 1.f, q1 = 1.f, q2 = 1.f, q3 = 1.f;
        float v0 = 1.f, v1 = 1.f, v2 = 1.f, v3 = 1.f;
        #pragma unroll
        for (int jp = 0; jp < 16; jp += 2) {
            float4 Ev = sE42[jp >> 1];
            float2 aA = __ldg(&t0r[jp * DD + k0]);
            float2 aB = __ldg(&t0r[(jp + 1) * DD + k0]);
            float2 bA = __ldg(&t1r[jp * DD + k1]);
            float2 bB = __ldg(&t1r[(jp + 1) * DD + k1]);
            q0 *= fmaf(Ev.x, aA.x, 1.f);
            q1 *= fmaf(Ev.y, aA.y, 1.f);
            q2 *= fmaf(Ev.z, aB.x, 1.f);
            q3 *= fmaf(Ev.w, aB.y, 1.f);
            v0 *= fmaf(Ev.x, bA.x, 1.f);
            v1 *= fmaf(Ev.y, bA.y, 1.f);
            v2 *= fmaf(Ev.z, bB.x, 1.f);
            v3 *= fmaf(Ev.w, bB.y, 1.f);
        }
        float er0 = ebr0 * sqrtf((q0 * q1) * (q2 * q3));
        float er1 = ebr1 * sqrtf((v0 * v1) * (v2 * v3));

        float s2 = er0 + er1;
        #pragma unroll
        for (int off = 16; off; off >>= 1) s2 += __shfl_xor_sync(0xffffffffu, s2, off);
        if (lane == 0) sredf[w] = s2;
        __syncthreads();                        // B4 (genuine combine)

        float Sr = (sredf[0] + sredf[1]) + (sredf[2] + sredf[3]);

        // ---- accept: Zf/Zr = sqrt(R) * Sf / Sr > u ----
        bool accv = sqrtf(Rt) * Sf > au * Sr;
        out[row * DD + k0] = (k0 == kstar && accv) ? (1.f - xk0) : xk0;
        out[row * DD + k1] = (k1 == kstar && accv) ? (1.f - xk1) : xk1;
    }
}

extern "C" void kernel_launch(void* const* d_in, const int* in_sizes, int n_in,
                              void* d_out, int out_size) {
    const float* x   = (const float*)d_in[0];
    const float* W   = (const float*)d_in[1];
    const float* b   = (const float*)d_in[2];
    const float* c   = (const float*)d_in[3];
    const float* gum = (const float*)d_in[4];
    const float* acc = (const float*)d_in[5];
    float* out = (float*)d_out;

    prep_kernel<<<8 + BB / 8, 256>>>(x, W, b, c);

    // PDL: gwg launches as prep's blocks trigger; it waits on prep's writes
    // via cudaGridDependencySynchronize() before touching the tables.
    cudaLaunchConfig_t cfg = {};
    cfg.gridDim  = dim3(BB / ROWS_PER_BLK, 1, 1);
    cfg.blockDim = dim3(128, 1, 1);
    cfg.dynamicSmemBytes = 0;
    cfg.stream = 0;
    cudaLaunchAttribute attrs[1];
    attrs[0].id = cudaLaunchAttributeProgrammaticStreamSerialization;
    attrs[0].val.programmaticStreamSerializationAllowed = 1;
    cfg.attrs = attrs;
    cfg.numAttrs = 1;
    cudaLaunchKernelEx(&cfg, gwg_kernel, x, gum, acc, out);
}

// round 12
// speedup vs baseline: 1.3272x; 1.3272x over previous
#include <cuda_runtime.h>

#define BB 1024
#define DD 256
#define HH 32

// Column tables: exp(+W)/exp(-W) interleaved by j-pair, [16][DD] float2 — coalesced
// across k in the per-dim passes.  Row tables: [DD][HH] — coalesced across j for the
// rank-1 kstar-row gather.
__device__ float  g_ewp[HH * DD];
__device__ float  g_ewm[HH * DD];
__device__ float  g_ewpR[DD * HH];
__device__ float  g_ewmR[DD * HH];
__device__ float2 g_eb[DD];          // (exp(+b/2), exp(-b/2))
__device__ float  g_E[BB * HH];      // E_j(row) = exp((x@W)_j + c_j)

// Prep: blocks 0..7 build tables; blocks 8..8+BB/8-1 compute E, 8 rows per block.
__global__ __launch_bounds__(256) void prep_kernel(
    const float* __restrict__ x,
    const float* __restrict__ W,
    const float* __restrict__ b,
    const float* __restrict__ c)
{
    const int bid = blockIdx.x;
    const int tid = threadIdx.x;
    if (bid < 8) {
        for (int t = bid * 256 + tid; t < DD * HH; t += 8 * 256) {
            int d = t >> 5;
            int j = t & 31;
            float w  = W[t];
            float ep = expf(w);
            float em = expf(-w);
            int idx = (j >> 1) * (DD * 2) + d * 2 + (j & 1);
            g_ewp[idx] = ep;
            g_ewm[idx] = em;
            g_ewpR[t] = ep;          // t = d*HH + j: row-major copy
            g_ewmR[t] = em;
        }
        int t = bid * 256 + tid;
        if (t < DD) {
            float bv = b[t];
            g_eb[t] = make_float2(expf(0.5f * bv), expf(-0.5f * bv));
        }
        cudaTriggerProgrammaticLaunchCompletion();
        return;
    }

    // ---- E for 8 rows: warp w covers d in [32w,32w+32), lane = j.
    //      Each W value is loaded once and reused across 8 rows (8 masks). ----
    __shared__ float ap[8][8][32];           // [warp][row][j]
    const int row0 = (bid - 8) * 8;
    const int w    = tid >> 5;
    const int lane = tid & 31;

    unsigned m[8];
    #pragma unroll
    for (int r = 0; r < 8; ++r)
        m[r] = __ballot_sync(0xffffffffu, x[(row0 + r) * DD + w * 32 + lane] != 0.0f);

    const float* Wb = W + (w * 32) * HH + lane;
    float acc[8] = {0.f, 0.f, 0.f, 0.f, 0.f, 0.f, 0.f, 0.f};
    #pragma unroll
    for (int i = 0; i < 32; ++i) {
        float wv = Wb[i * HH];
        #pragma unroll
        for (int r = 0; r < 8; ++r)
            if (m[r] & (1u << i)) acc[r] += wv;
    }
    #pragma unroll
    for (int r = 0; r < 8; ++r) ap[w][r][lane] = acc[r];
    __syncthreads();

    // warp w finishes row (row0 + w)
    float a = c[lane];
    #pragma unroll
    for (int ww = 0; ww < 8; ++ww) a += ap[ww][w][lane];
    g_E[(row0 + w) * HH + lane] = expf(a);
    cudaTriggerProgrammaticLaunchCompletion();
}

__device__ __forceinline__ unsigned fmono(float f) {
    unsigned u = __float_as_uint(f);
    return (u & 0x80000000u) ? ~u : (u | 0x80000000u);
}

__global__ __launch_bounds__(256) void gwg_kernel(
    const float* __restrict__ x,
    const float* __restrict__ gum,
    const float* __restrict__ acc,
    float* __restrict__ out)
{
    __shared__ float xs[DD];
    __shared__ __align__(16) float sEf[8][HH];   // per-warp copy of E_j
    __shared__ __align__(16) float sE2[8][HH];   // per-warp copy of E'_j
    __shared__ float sredf[8];
    __shared__ uint2 sredk[8];                   // (fmono(key), idx) per warp

    const int row  = blockIdx.x;
    const int tid  = threadIdx.x;
    const int w    = tid >> 5;
    const int lane = tid & 31;
    const int k    = tid;                        // one dim per thread

    // prep-independent front work (overlaps prep via PDL)
    float xk = x[row * DD + k];
    float u  = gum[row * DD + k];
    float au = acc[row];
    xs[k] = xk;
    float z = -logf(u + 1e-9f) + 1e-9f;

    cudaGridDependencySynchronize();

    float2 ebv = g_eb[k];

    // each warp keeps its own E copy -> no cross-warp wait before forward pass
    float E = g_E[row * HH + lane];
    sEf[w][lane] = E;
    __syncwarp();

    // ---- forward: p~_k = prod_j (1 + E_j e^{delta_k w_kj});  ek = eb * sqrt ----
    const float2* t0 = (const float2*)((xk == 0.0f) ? g_ewp : g_ewm);
    const float   eb = (xk == 0.0f) ? ebv.x : ebv.y;
    const float4* sE4f = (const float4*)sEf[w];

    float p0 = 1.f, p1 = 1.f, p2 = 1.f, p3 = 1.f;
    #pragma unroll
    for (int jp = 0; jp < 16; jp += 2) {
        float4 Ev = sE4f[jp >> 1];
        float2 eA = __ldg(&t0[jp * DD + k]);
        float2 eB = __ldg(&t0[(jp + 1) * DD + k]);
        p0 *= fmaf(Ev.x, eA.x, 1.f);
        p1 *= fmaf(Ev.y, eA.y, 1.f);
        p2 *= fmaf(Ev.z, eB.x, 1.f);
        p3 *= fmaf(Ev.w, eB.y, 1.f);
    }
    float ek  = eb * sqrtf((p0 * p1) * (p2 * p3));
    float key = ek / z;

    // warp sum (5 shfl) + warp argmax (redux + ballot + 1 shfl)
    float s = ek;
    #pragma unroll
    for (int off = 16; off; off >>= 1) s += __shfl_xor_sync(0xffffffffu, s, off);
    unsigned km   = fmono(key);
    unsigned wmax = __reduce_max_sync(0xffffffffu, km);
    unsigned ball = __ballot_sync(0xffffffffu, km == wmax);
    int      wki  = w * 32 + (__ffs(ball) - 1);
    if (lane == 0) { sredf[w] = s; sredk[w] = make_uint2(wmax, (unsigned)wki); }
    __syncthreads();                           // B2 (genuine combine)

    // ---- every thread combines 8 warp partials via broadcast LDS ----
    float Sf;
    int   kstar;
    {
        Sf = ((sredf[0] + sredf[1]) + (sredf[2] + sredf[3]))
           + ((sredf[4] + sredf[5]) + (sredf[6] + sredf[7]));
        uint2 c0 = sredk[0], c1 = sredk[1], c2 = sredk[2], c3 = sredk[3];
        uint2 c4 = sredk[4], c5 = sredk[5], c6 = sredk[6], c7 = sredk[7];
        uint2 mA = (c1.x > c0.x) ? c1 : c0;    // distinct warps -> no ties
        uint2 mB = (c3.x > c2.x) ? c3 : c2;
        uint2 mC = (c5.x > c4.x) ? c5 : c4;
        uint2 mD = (c7.x > c6.x) ? c7 : c6;
        // tie across warps: keep lowest index
        uint2 mAB = (mB.x > mA.x || (mB.x == mA.x && mB.y < mA.y)) ? mB : mA;
        uint2 mCD = (mD.x > mC.x || (mD.x == mC.x && mD.y < mC.y)) ? mD : mC;
        uint2 mm  = (mCD.x > mAB.x || (mCD.x == mAB.x && mCD.y < mAB.y)) ? mCD : mAB;
        kstar = (int)mm.y;
    }

    // ---- rank-1 update, per-warp redundant: coalesced row read; R in register ----
    float Rt;
    {
        float xks = xs[kstar];                 // visible: written pre-B2
        const float* rowt = (xks == 0.0f) ? g_ewpR : g_ewmR;
        float mj  = __ldg(&rowt[kstar * HH + lane]);
        float E2  = E * mj;
        sE2[w][lane] = E2;
        float rr = (1.f + E2) / (1.f + E);
        #pragma unroll
        for (int off = 16; off; off >>= 1) rr *= __shfl_xor_sync(0xffffffffu, rr, off);
        Rt = rr;
        __syncwarp();
    }

    // ---- reverse pass at x_delta: table flips only for the kstar dim ----
    const float2* t0r = (k == kstar) ? ((xk == 0.0f) ? (const float2*)g_ewm : (const float2*)g_ewp) : t0;
    const float   eb2 = (k == kstar) ? ((xk == 0.0f) ? ebv.y : ebv.x) : eb;
    const float4* sE42 = (const float4*)sE2[w];

    float q0 = 1.f, q1 = 1.f, q2 = 1.f, q3 = 1.f;
    #pragma unroll
    for (int jp = 0; jp < 16; jp += 2) {
        float4 Ev = sE42[jp >> 1];
        float2 eA = __ldg(&t0r[jp * DD + k]);
        float2 eB = __ldg(&t0r[(jp + 1) * DD + k]);
        q0 *= fmaf(Ev.x, eA.x, 1.f);
        q1 *= fmaf(Ev.y, eA.y, 1.f);
        q2 *= fmaf(Ev.z, eB.x, 1.f);
        q3 *= fmaf(Ev.w, eB.y, 1.f);
    }
    float ek2 = eb2 * sqrtf((q0 * q1) * (q2 * q3));

    float s2 = ek2;
    #pragma unroll
    for (int off = 16; off; off >>= 1) s2 += __shfl_xor_sync(0xffffffffu, s2, off);
    if (lane == 0) sredf[w] = s2;
    __syncthreads();                           // B4 (genuine combine)

    float Sr = ((sredf[0] + sredf[1]) + (sredf[2] + sredf[3]))
             + ((sredf[4] + sredf[5]) + (sredf[6] + sredf[7]));

    // ---- accept: Zf/Zr = sqrt(R) * Sf / Sr > u ----
    bool accv = sqrtf(Rt) * Sf > au * Sr;
    out[row * DD + k] = (k == kstar && accv) ? (1.f - xk) : xk;
}

extern "C" void kernel_launch(void* const* d_in, const int* in_sizes, int n_in,
                              void* d_out, int out_size) {
    const float* x   = (const float*)d_in[0];
    const float* W   = (const float*)d_in[1];
    const float* b   = (const float*)d_in[2];
    const float* c   = (const float*)d_in[3];
    const float* gum = (const float*)d_in[4];
    const float* acc = (const float*)d_in[5];
    float* out = (float*)d_out;

    prep_kernel<<<8 + BB / 8, 256>>>(x, W, b, c);

    // PDL: gwg launches as prep's blocks trigger; it does prep-independent
    // front work, then cudaGridDependencySynchronize() before reading tables.
    cudaLaunchConfig_t cfg = {};
    cfg.gridDim  = dim3(BB, 1, 1);
    cfg.blockDim = dim3(256, 1, 1);
    cfg.dynamicSmemBytes = 0;
    cfg.stream = 0;
    cudaLaunchAttribute attrs[1];
    attrs[0].id = cudaLaunchAttributeProgrammaticStreamSerialization;
    attrs[0].val.programmaticStreamSerializationAllowed = 1;
    cfg.attrs = attrs;
    cfg.numAttrs = 1;
    cudaLaunchKernelEx(&cfg, gwg_kernel, x, gum, acc, out);
}

// round 13
// speedup vs baseline: 1.3682x; 1.0309x over previous
#include <cuda_runtime.h>

#define BB 1024
#define DD 256
#define HH 32

// Column tables: exp(+W)/exp(-W) interleaved by j-pair, [16][DD] float2 — coalesced
// across k.  Row tables: [DD][HH] — coalesced across j for the rank-1 gather.
__device__ float  g_ewp[HH * DD];
__device__ float  g_ewm[HH * DD];
__device__ float  g_ewpR[DD * HH];
__device__ float  g_ewmR[DD * HH];
__device__ float2 g_eb[DD];          // (exp(+b/2), exp(-b/2))
__device__ float  g_E[BB * HH];      // E_j(row) = exp((x@W)_j + c_j)

// Prep: blocks 0..7 build tables; blocks 8..8+BB/8-1 compute E, 8 rows per block.
__global__ __launch_bounds__(256) void prep_kernel(
    const float* __restrict__ x,
    const float* __restrict__ W,
    const float* __restrict__ b,
    const float* __restrict__ c)
{
    const int bid = blockIdx.x;
    const int tid = threadIdx.x;
    if (bid < 8) {
        for (int t = bid * 256 + tid; t < DD * HH; t += 8 * 256) {
            int d = t >> 5;
            int j = t & 31;
            float w  = W[t];
            float ep = expf(w);
            float em = expf(-w);
            int idx = (j >> 1) * (DD * 2) + d * 2 + (j & 1);
            g_ewp[idx] = ep;
            g_ewm[idx] = em;
            g_ewpR[t] = ep;
            g_ewmR[t] = em;
        }
        int t = bid * 256 + tid;
        if (t < DD) {
            float bv = b[t];
            g_eb[t] = make_float2(expf(0.5f * bv), expf(-0.5f * bv));
        }
        cudaTriggerProgrammaticLaunchCompletion();
        return;
    }

    __shared__ float ap[8][8][32];           // [warp][row][j]
    const int row0 = (bid - 8) * 8;
    const int w    = tid >> 5;
    const int lane = tid & 31;

    unsigned m[8];
    #pragma unroll
    for (int r = 0; r < 8; ++r)
        m[r] = __ballot_sync(0xffffffffu, x[(row0 + r) * DD + w * 32 + lane] != 0.0f);

    const float* Wb = W + (w * 32) * HH + lane;
    float acc[8] = {0.f, 0.f, 0.f, 0.f, 0.f, 0.f, 0.f, 0.f};
    #pragma unroll
    for (int i = 0; i < 32; ++i) {
        float wv = Wb[i * HH];
        #pragma unroll
        for (int r = 0; r < 8; ++r)
            if (m[r] & (1u << i)) acc[r] += wv;
    }
    #pragma unroll
    for (int r = 0; r < 8; ++r) ap[w][r][lane] = acc[r];
    __syncthreads();

    float a = c[lane];
    #pragma unroll
    for (int ww = 0; ww < 8; ++ww) a += ap[ww][w][lane];
    g_E[(row0 + w) * HH + lane] = expf(a);
    cudaTriggerProgrammaticLaunchCompletion();
}

__device__ __forceinline__ unsigned fmono(float f) {
    unsigned u = __float_as_uint(f);
    return (u & 0x80000000u) ? ~u : (u | 0x80000000u);
}

// 2 rows per block, interleaved: 256 threads, 1 dim/thread/row, 2 logits/thread.
__global__ __launch_bounds__(256, 4) void gwg_kernel(
    const float* __restrict__ x,
    const float* __restrict__ gum,
    const float* __restrict__ acc,
    float* __restrict__ out)
{
    __shared__ float xsA[DD];
    __shared__ float xsB[DD];
    __shared__ __align__(16) float sEfA[8][HH], sEfB[8][HH];
    __shared__ __align__(16) float sE2A[8][HH], sE2B[8][HH];
    __shared__ float sredfA[8], sredfB[8];
    __shared__ uint2 sredkA[8], sredkB[8];

    const int tid  = threadIdx.x;
    const int w    = tid >> 5;
    const int lane = tid & 31;
    const int k    = tid;
    const int rowA = blockIdx.x * 2;
    const int rowB = rowA + 1;

    // prep-independent front work (overlaps prep via PDL)
    float xkA = x[rowA * DD + k];
    float xkB = x[rowB * DD + k];
    float uA  = gum[rowA * DD + k];
    float uB  = gum[rowB * DD + k];
    float auA = acc[rowA];
    float auB = acc[rowB];
    xsA[k] = xkA;
    xsB[k] = xkB;
    float zA = -logf(uA + 1e-9f) + 1e-9f;
    float zB = -logf(uB + 1e-9f) + 1e-9f;

    cudaGridDependencySynchronize();

    float2 ebv = g_eb[k];                    // shared by both rows (same k)

    float EA = g_E[rowA * HH + lane];
    float EB = g_E[rowB * HH + lane];
    sEfA[w][lane] = EA;
    sEfB[w][lane] = EB;
    __syncwarp();

    // ---- forward, both rows interleaved ----
    const float2* tA = (const float2*)((xkA == 0.0f) ? g_ewp : g_ewm);
    const float2* tB = (const float2*)((xkB == 0.0f) ? g_ewp : g_ewm);
    const float ebfA = (xkA == 0.0f) ? ebv.x : ebv.y;
    const float ebfB = (xkB == 0.0f) ? ebv.x : ebv.y;
    const float4* E4A = (const float4*)sEfA[w];
    const float4* E4B = (const float4*)sEfB[w];

    float pA0 = 1.f, pA1 = 1.f, pA2 = 1.f, pA3 = 1.f;
    float pB0 = 1.f, pB1 = 1.f, pB2 = 1.f, pB3 = 1.f;
    #pragma unroll
    for (int jp = 0; jp < 16; jp += 2) {
        float4 EvA = E4A[jp >> 1];
        float4 EvB = E4B[jp >> 1];
        float2 aA = __ldg(&tA[jp * DD + k]);
        float2 aB = __ldg(&tA[(jp + 1) * DD + k]);
        float2 bA = __ldg(&tB[jp * DD + k]);
        float2 bB = __ldg(&tB[(jp + 1) * DD + k]);
        pA0 *= fmaf(EvA.x, aA.x, 1.f);
        pA1 *= fmaf(EvA.y, aA.y, 1.f);
        pA2 *= fmaf(EvA.z, aB.x, 1.f);
        pA3 *= fmaf(EvA.w, aB.y, 1.f);
        pB0 *= fmaf(EvB.x, bA.x, 1.f);
        pB1 *= fmaf(EvB.y, bA.y, 1.f);
        pB2 *= fmaf(EvB.z, bB.x, 1.f);
        pB3 *= fmaf(EvB.w, bB.y, 1.f);
    }
    float ekA = ebfA * sqrtf((pA0 * pA1) * (pA2 * pA3));
    float ekB = ebfB * sqrtf((pB0 * pB1) * (pB2 * pB3));
    float keyA = ekA / zA;
    float keyB = ekB / zB;

    // warp reductions, both rows interleaved
    float sA = ekA, sB = ekB;
    #pragma unroll
    for (int off = 16; off; off >>= 1) {
        sA += __shfl_xor_sync(0xffffffffu, sA, off);
        sB += __shfl_xor_sync(0xffffffffu, sB, off);
    }
    unsigned kmA = fmono(keyA),  kmB = fmono(keyB);
    unsigned mxA = __reduce_max_sync(0xffffffffu, kmA);
    unsigned mxB = __reduce_max_sync(0xffffffffu, kmB);
    unsigned blA = __ballot_sync(0xffffffffu, kmA == mxA);
    unsigned blB = __ballot_sync(0xffffffffu, kmB == mxB);
    int wkiA = w * 32 + (__ffs(blA) - 1);
    int wkiB = w * 32 + (__ffs(blB) - 1);
    if (lane == 0) {
        sredfA[w] = sA;  sredkA[w] = make_uint2(mxA, (unsigned)wkiA);
        sredfB[w] = sB;  sredkB[w] = make_uint2(mxB, (unsigned)wkiB);
    }
    __syncthreads();                         // B2, serves both rows

    float SfA, SfB;
    int   ksA, ksB;
    {
        SfA = ((sredfA[0] + sredfA[1]) + (sredfA[2] + sredfA[3]))
            + ((sredfA[4] + sredfA[5]) + (sredfA[6] + sredfA[7]));
        SfB = ((sredfB[0] + sredfB[1]) + (sredfB[2] + sredfB[3]))
            + ((sredfB[4] + sredfB[5]) + (sredfB[6] + sredfB[7]));
        uint2 a0 = sredkA[0], a1 = sredkA[1], a2 = sredkA[2], a3 = sredkA[3];
        uint2 a4 = sredkA[4], a5 = sredkA[5], a6 = sredkA[6], a7 = sredkA[7];
        uint2 mA = (a1.x > a0.x) ? a1 : a0;
        uint2 mB = (a3.x > a2.x) ? a3 : a2;
        uint2 mC = (a5.x > a4.x) ? a5 : a4;
        uint2 mD = (a7.x > a6.x) ? a7 : a6;
        uint2 mAB = (mB.x > mA.x || (mB.x == mA.x && mB.y < mA.y)) ? mB : mA;
        uint2 mCD = (mD.x > mC.x || (mD.x == mC.x && mD.y < mC.y)) ? mD : mC;
        uint2 mm  = (mCD.x > mAB.x || (mCD.x == mAB.x && mCD.y < mAB.y)) ? mCD : mAB;
        ksA = (int)mm.y;
        uint2 b0 = sredkB[0], b1 = sredkB[1], b2 = sredkB[2], b3 = sredkB[3];
        uint2 b4 = sredkB[4], b5 = sredkB[5], b6 = sredkB[6], b7 = sredkB[7];
        uint2 nA = (b1.x > b0.x) ? b1 : b0;
        uint2 nB = (b3.x > b2.x) ? b3 : b2;
        uint2 nC = (b5.x > b4.x) ? b5 : b4;
        uint2 nD = (b7.x > b6.x) ? b7 : b6;
        uint2 nAB = (nB.x > nA.x || (nB.x == nA.x && nB.y < nA.y)) ? nB : nA;
        uint2 nCD = (nD.x > nC.x || (nD.x == nC.x && nD.y < nC.y)) ? nD : nC;
        uint2 nn  = (nCD.x > nAB.x || (nCD.x == nAB.x && nCD.y < nAB.y)) ? nCD : nAB;
        ksB = (int)nn.y;
    }

    // ---- rank-1 updates, per-warp redundant, both rows interleaved ----
    float RtA, RtB;
    {
        float xksA = xsA[ksA];
        float xksB = xsB[ksB];
        const float* rtA = (xksA == 0.0f) ? g_ewpR : g_ewmR;
        const float* rtB = (xksB == 0.0f) ? g_ewpR : g_ewmR;
        float mjA = __ldg(&rtA[ksA * HH + lane]);
        float mjB = __ldg(&rtB[ksB * HH + lane]);
        float E2A = EA * mjA;
        float E2B = EB * mjB;
        sE2A[w][lane] = E2A;
        sE2B[w][lane] = E2B;
        float rA = (1.f + E2A) / (1.f + EA);
        float rB = (1.f + E2B) / (1.f + EB);
        #pragma unroll
        for (int off = 16; off; off >>= 1) {
            rA *= __shfl_xor_sync(0xffffffffu, rA, off);
            rB *= __shfl_xor_sync(0xffffffffu, rB, off);
        }
        RtA = rA;  RtB = rB;
        __syncwarp();
    }

    // ---- reverse, both rows interleaved; table flips only at kstar ----
    const float2* tAr = (k == ksA) ? ((xkA == 0.0f) ? (const float2*)g_ewm : (const float2*)g_ewp) : tA;
    const float2* tBr = (k == ksB) ? ((xkB == 0.0f) ? (const float2*)g_ewm : (const float2*)g_ewp) : tB;
    const float ebrA = (k == ksA) ? ((xkA == 0.0f) ? ebv.y : ebv.x) : ebfA;
    const float ebrB = (k == ksB) ? ((xkB == 0.0f) ? ebv.y : ebv.x) : ebfB;
    const float4* F4A = (const float4*)sE2A[w];
    const float4* F4B = (const float4*)sE2B[w];

    float qA0 = 1.f, qA1 = 1.f, qA2 = 1.f, qA3 = 1.f;
    float qB0 = 1.f, qB1 = 1.f, qB2 = 1.f, qB3 = 1.f;
    #pragma unroll
    for (int jp = 0; jp < 16; jp += 2) {
        float4 EvA = F4A[jp >> 1];
        float4 EvB = F4B[jp >> 1];
        float2 aA = __ldg(&tAr[jp * DD + k]);
        float2 aB = __ldg(&tAr[(jp + 1) * DD + k]);
        float2 bA = __ldg(&tBr[jp * DD + k]);
        float2 bB = __ldg(&tBr[(jp + 1) * DD + k]);
        qA0 *= fmaf(EvA.x, aA.x, 1.f);
        qA1 *= fmaf(EvA.y, aA.y, 1.f);
        qA2 *= fmaf(EvA.z, aB.x, 1.f);
        qA3 *= fmaf(EvA.w, aB.y, 1.f);
        qB0 *= fmaf(EvB.x, bA.x, 1.f);
        qB1 *= fmaf(EvB.y, bA.y, 1.f);
        qB2 *= fmaf(EvB.z, bB.x, 1.f);
        qB3 *= fmaf(EvB.w, bB.y, 1.f);
    }
    float ekA2 = ebrA * sqrtf((qA0 * qA1) * (qA2 * qA3));
    float ekB2 = ebrB * sqrtf((qB0 * qB1) * (qB2 * qB3));

    float s2A = ekA2, s2B = ekB2;
    #pragma unroll
    for (int off = 16; off; off >>= 1) {
        s2A += __shfl_xor_sync(0xffffffffu, s2A, off);
        s2B += __shfl_xor_sync(0xffffffffu, s2B, off);
    }
    if (lane == 0) { sredfA[w] = s2A; sredfB[w] = s2B; }
    __syncthreads();                         // B4, serves both rows

    float SrA = ((sredfA[0] + sredfA[1]) + (sredfA[2] + sredfA[3]))
              + ((sredfA[4] + sredfA[5]) + (sredfA[6] + sredfA[7]));
    float SrB = ((sredfB[0] + sredfB[1]) + (sredfB[2] + sredfB[3]))
              + ((sredfB[4] + sredfB[5]) + (sredfB[6] + sredfB[7]));

    bool accA = sqrtf(RtA) * SfA > auA * SrA;
    bool accB = sqrtf(RtB) * SfB > auB * SrB;
    out[rowA * DD + k] = (k == ksA && accA) ? (1.f - xkA) : xkA;
    out[rowB * DD + k] = (k == ksB && accB) ? (1.f - xkB) : xkB;
}

extern "C" void kernel_launch(void* const* d_in, const int* in_sizes, int n_in,
                              void* d_out, int out_size) {
    const float* x   = (const float*)d_in[0];
    const float* W   = (const float*)d_in[1];
    const float* b   = (const float*)d_in[2];
    const float* c   = (const float*)d_in[3];
    const float* gum = (const float*)d_in[4];
    const float* acc = (const float*)d_in[5];
    float* out = (float*)d_out;

    prep_kernel<<<8 + BB / 8, 256>>>(x, W, b, c);

    cudaLaunchConfig_t cfg = {};
    cfg.gridDim  = dim3(BB / 2, 1, 1);
    cfg.blockDim = dim3(256, 1, 1);
    cfg.dynamicSmemBytes = 0;
    cfg.stream = 0;
    cudaLaunchAttribute attrs[1];
    attrs[0].id = cudaLaunchAttributeProgrammaticStreamSerialization;
    attrs[0].val.programmaticStreamSerializationAllowed = 1;
    cfg.attrs = attrs;
    cfg.numAttrs = 1;
    cudaLaunchKernelEx(&cfg, gwg_kernel, x, gum, acc, out);
}